// round 2
// baseline (speedup 1.0000x reference)
#include <cuda_runtime.h>

// out = x + delta for the NVM shift op.  x: [262144, 512] fp32.
// Row layout (D=512):
//   col 0: OP_SHL, col 1: OP_SHR, col 2: MARK_AX  (flags, >0.5)
//   cols 16-31 : ALU_LO      (argmax -> a_lo)
//   cols 32-47 : ALU_HI      (argmax -> a_hi)
//   cols 48-63 : AX_CARRY_LO (argmax -> shift, clipped to [0,7])
//   cols 64-79 : OUTPUT_LO   (+= active at 64 + r_lo)
//   cols 80-95 : OUTPUT_HI   (+= active at 80 + r_hi)
// a = a_lo + 16*a_hi; result = shl ? (a<<s)&255 : a>>s  (integer-exact vs the
// reference's fp32 magic-floor for these value ranges).
//
// One WARP per row. Lane l loads float4 indices {l, l+32, l+64, l+96} of the
// row (4 independent front-batched LDG.128 -> MLP=4). Lane l's first float4
// v0 covers cols 4l..4l+3, so all decode fields AND both output fields
// (cols 0..127) live in v0 across the 32 lanes. 8 warps (8 rows) per block.

__global__ __launch_bounds__(256) void shift_kernel(const float4* __restrict__ x,
                                                    float4* __restrict__ out) {
    const int warp = threadIdx.x >> 5;
    const int lane = threadIdx.x & 31;
    const long long row = (long long)blockIdx.x * 8 + warp;

    const float4* __restrict__ xin = x + row * 128;
    float4* __restrict__ xout = out + row * 128;

    // Front-batched independent loads (MLP_p1 = 4)
    float4 v0 = xin[lane];
    float4 v1 = xin[lane + 32];
    float4 v2 = xin[lane + 64];
    float4 v3 = xin[lane + 96];

    // ---- decode on v0 (cols 4*lane .. 4*lane+3) ----
    // lanes 4-7  -> ALU_LO (cols 16-31), lanes 8-11 -> ALU_HI (32-47),
    // lanes 12-15 -> AX_CARRY_LO (48-63). Local argmax then group-of-4
    // shuffle reduction with first-max-wins tie-break (matches jnp.argmax).
    float m = -1e30f;
    int mi = 0x7fffffff;
    if (lane >= 4 && lane < 16) {
        const int base = (lane & 3) * 4;
        float vals[4] = {v0.x, v0.y, v0.z, v0.w};
        m = vals[0];
        mi = base;
        #pragma unroll
        for (int j = 1; j < 4; j++) {
            if (vals[j] > m) { m = vals[j]; mi = base + j; }
        }
    }
    #pragma unroll
    for (int off = 1; off <= 2; off <<= 1) {
        float om = __shfl_xor_sync(0xffffffffu, m, off);
        int omi = __shfl_xor_sync(0xffffffffu, mi, off);
        if (om > m || (om == m && omi < mi)) { m = om; mi = omi; }
    }
    const int a_lo = __shfl_sync(0xffffffffu, mi, 4);
    const int a_hi = __shfl_sync(0xffffffffu, mi, 8);
    int shift     = __shfl_sync(0xffffffffu, mi, 12);

    // flags from lane 0 (cols 0,1,2 = v0.x,v0.y,v0.z)
    int flags = 0;
    if (lane == 0) {
        flags = (v0.x > 0.5f ? 1 : 0) | (v0.y > 0.5f ? 2 : 0) | (v0.z > 0.5f ? 4 : 0);
    }
    flags = __shfl_sync(0xffffffffu, flags, 0);

    const bool mark = (flags & 4) != 0;
    const bool active_shl = ((flags & 1) != 0) && mark;
    const bool active_shr = ((flags & 2) != 0) && mark;

    if (active_shl || active_shr) {
        if (shift > 7) shift = 7;
        const int a = a_lo + (a_hi << 4);                     // [0,255]
        const int result = active_shl ? ((a << shift) & 255)
                                      : (a >> shift);
        const int col_lo = 64 + (result & 15);
        const int col_hi = 80 + ((result >> 4) & 15);

        // lanes 16-23 own cols 64..95 within v0; add in-register before store
        const int myc = lane << 2;
        float* vf = reinterpret_cast<float*>(&v0);
        if ((unsigned)(col_lo - myc) < 4u) vf[col_lo - myc] += 1.0f;
        if ((unsigned)(col_hi - myc) < 4u) vf[col_hi - myc] += 1.0f;
    }

    xout[lane]      = v0;
    xout[lane + 32] = v1;
    xout[lane + 64] = v2;
    xout[lane + 96] = v3;
}

extern "C" void kernel_launch(void* const* d_in, const int* in_sizes, int n_in,
                              void* d_out, int out_size) {
    const float4* x = (const float4*)d_in[0];
    float4* out = (float4*)d_out;
    const int rows = in_sizes[0] / 512;        // 262144, divisible by 8
    shift_kernel<<<rows / 8, 256>>>(x, out);
}

// round 4
// speedup vs baseline: 1.0020x; 1.0020x over previous
#include <cuda_runtime.h>

// out = x + delta for the NVM shift op.  x: [262144, 512] fp32.
// Row layout (D=512):
//   col 0: OP_SHL, col 1: OP_SHR, col 2: MARK_AX  (flags, >0.5)
//   cols 16-31 : ALU_LO      (argmax -> a_lo)
//   cols 32-47 : ALU_HI      (argmax -> a_hi)
//   cols 48-63 : AX_CARRY_LO (argmax -> shift, clipped to [0,7])
//   cols 64-79 : OUTPUT_LO   (+= active at 64 + r_lo)
//   cols 80-95 : OUTPUT_HI   (+= active at 80 + r_hi)
// a = a_lo + 16*a_hi; result = shl ? (a<<s)&255 : a>>s  (integer-exact vs the
// reference's fp32 magic-floor for these value ranges).
//
// One WARP per row, MLP=4 front-batched LDG.128 per lane. Streaming cache
// hints (__ldcs/__stcs): both streams are use-once (1 GB >> L2), so evict-
// first policy avoids the read and write streams thrashing each other in L2.

__global__ __launch_bounds__(256) void shift_kernel(const float4* __restrict__ x,
                                                    float4* __restrict__ out) {
    const int warp = threadIdx.x >> 5;
    const int lane = threadIdx.x & 31;
    const long long row = (long long)blockIdx.x * 8 + warp;

    const float4* __restrict__ xin = x + row * 128;
    float4* __restrict__ xout = out + row * 128;

    // Front-batched independent streaming loads (MLP_p1 = 4)
    float4 v0 = __ldcs(xin + lane);
    float4 v1 = __ldcs(xin + lane + 32);
    float4 v2 = __ldcs(xin + lane + 64);
    float4 v3 = __ldcs(xin + lane + 96);

    // ---- decode on v0 (cols 4*lane .. 4*lane+3) ----
    // lanes 4-7  -> ALU_LO (16-31), lanes 8-11 -> ALU_HI (32-47),
    // lanes 12-15 -> AX_CARRY_LO (48-63). Local argmax, then group-of-4
    // shuffle reduction with first-max-wins tie-break (matches jnp.argmax).
    float m = -1e30f;
    int mi = 0x7fffffff;
    if (lane >= 4 && lane < 16) {
        const int base = (lane & 3) * 4;
        float vals[4] = {v0.x, v0.y, v0.z, v0.w};
        m = vals[0];
        mi = base;
        #pragma unroll
        for (int j = 1; j < 4; j++) {
            if (vals[j] > m) { m = vals[j]; mi = base + j; }
        }
    }
    #pragma unroll
    for (int off = 1; off <= 2; off <<= 1) {
        float om = __shfl_xor_sync(0xffffffffu, m, off);
        int omi = __shfl_xor_sync(0xffffffffu, mi, off);
        if (om > m || (om == m && omi < mi)) { m = om; mi = omi; }
    }
    const int a_lo = __shfl_sync(0xffffffffu, mi, 4);
    const int a_hi = __shfl_sync(0xffffffffu, mi, 8);
    int shift     = __shfl_sync(0xffffffffu, mi, 12);

    // flags from lane 0 (cols 0,1,2 = v0.x,v0.y,v0.z)
    int flags = 0;
    if (lane == 0) {
        flags = (v0.x > 0.5f ? 1 : 0) | (v0.y > 0.5f ? 2 : 0) | (v0.z > 0.5f ? 4 : 0);
    }
    flags = __shfl_sync(0xffffffffu, flags, 0);

    const bool mark = (flags & 4) != 0;
    const bool active_shl = ((flags & 1) != 0) && mark;
    const bool active_shr = ((flags & 2) != 0) && mark;

    if (active_shl || active_shr) {
        if (shift > 7) shift = 7;
        const int a = a_lo + (a_hi << 4);                     // [0,255]
        const int result = active_shl ? ((a << shift) & 255)
                                      : (a >> shift);
        const int col_lo = 64 + (result & 15);
        const int col_hi = 80 + ((result >> 4) & 15);

        // lanes 16-23 own cols 64..95 within v0; add in-register before store
        const int myc = lane << 2;
        float* vf = reinterpret_cast<float*>(&v0);
        if ((unsigned)(col_lo - myc) < 4u) vf[col_lo - myc] += 1.0f;
        if ((unsigned)(col_hi - myc) < 4u) vf[col_hi - myc] += 1.0f;
    }

    __stcs(xout + lane,      v0);
    __stcs(xout + lane + 32, v1);
    __stcs(xout + lane + 64, v2);
    __stcs(xout + lane + 96, v3);
}

extern "C" void kernel_launch(void* const* d_in, const int* in_sizes, int n_in,
                              void* d_out, int out_size) {
    const float4* x = (const float4*)d_in[0];
    float4* out = (float4*)d_out;
    const int rows = in_sizes[0] / 512;        // 262144, divisible by 8
    shift_kernel<<<rows / 8, 256>>>(x, out);
}